// round 4
// baseline (speedup 1.0000x reference)
#include <cuda_runtime.h>

// Cost volume s2: B=4, C=32, H=W=256, D=9, 8 groups of 4 channels.
// y-offset is 0 -> 1D lerp in x; res span 0.8 < 1 px -> 3 taps/side cover all d.
// Abs-form hat lerp:  w = P1 + t*S + |t|*Dd,
//   S = (P2-P0)/2, Dd = (P2+P0)/2 - P1, t = x-(n+1) in [-1,1].
// Left/right packed in f32x2 lanes (FFMA2); t advanced incrementally (packed),
// |t| via 64-bit mask -> 3 cheap ops per d, 2 packed FMAs per (d,channel).

typedef unsigned long long u64;

constexpr int Wd = 256, Cn = 32, Bn = 4, Dn = 9, Gn = 8, CPG = 4;
constexpr int HW = 256 * 256;

__device__ __forceinline__ u64 pk(float a, float b) {
    u64 r; asm("mov.b64 %0, {%1, %2};" : "=l"(r) : "f"(a), "f"(b)); return r;
}
__device__ __forceinline__ void upk(float& a, float& b, u64 v) {
    asm("mov.b64 {%0, %1}, %2;" : "=f"(a), "=f"(b) : "l"(v));
}
__device__ __forceinline__ u64 ffma2(u64 a, u64 b, u64 c) {
    u64 d; asm("fma.rn.f32x2 %0, %1, %2, %3;" : "=l"(d) : "l"(a), "l"(b), "l"(c));
    return d;
}
__device__ __forceinline__ u64 add2(u64 a, u64 b) {
    u64 d; asm("add.rn.f32x2 %0, %1, %2;" : "=l"(d) : "l"(a), "l"(b));
    return d;
}

__global__ __launch_bounds__(256, 4) void cost_volume_kernel(
    const float* __restrict__ fref,
    const float* __restrict__ fls,
    const float* __restrict__ frs,
    const float* __restrict__ dinit,
    float* __restrict__ out)
{
    const int idx = blockIdx.x * 256 + threadIdx.x;   // B*H*W = 262144
    const int b  = idx >> 16;
    const int hw = idx & (HW - 1);
    const int w  = idx & (Wd - 1);

    const float disp = __ldg(dinit + idx);
    const float wf = (float)w;

    // Left taps at n_l..n_l+2, n_l = floor(x_l at d=0); x_l increases with d.
    const float xl0 = wf + disp - 0.4f;
    const float fll = floorf(xl0);
    const int   n_l = (int)fll;
    const float tl0 = xl0 - fll - 1.0f;            // t_l at d=0, in [-1, 0)

    // Right taps at n_r..n_r+2, n_r = floor(x_r at d=8); x_r decreases with d.
    const float xr0 = wf - disp + 0.4f;            // x_r at d=0 (max over d)
    const float flr = floorf(xr0 - 0.8f);          // floor of min x_r (d=8)
    const int   n_r = (int)flr;
    const float tr0 = xr0 - flr - 1.0f;            // t_r at d=0

    const u64 t02   = pk(tl0, tr0);
    const u64 step2 = pk(0.1f, -0.1f);
    const u64 amask = 0x7FFFFFFF7FFFFFFFull;

    const bool vL0 = (unsigned)(n_l)     < (unsigned)Wd;
    const bool vL1 = (unsigned)(n_l + 1) < (unsigned)Wd;
    const bool vL2 = (unsigned)(n_l + 2) < (unsigned)Wd;
    const bool vR0 = (unsigned)(n_r)     < (unsigned)Wd;
    const bool vR1 = (unsigned)(n_r + 1) < (unsigned)Wd;
    const bool vR2 = (unsigned)(n_r + 2) < (unsigned)Wd;

    const int rowbase0 = b * Cn * HW + (hw - w);   // channel-0 row start
    float* outp = out + b * (Gn * Dn * HW) + hw;

    const float k2 = 1.0f / 12.0f;   // (1/3 var) * (1/4 group mean)
    const float k1 = 1.0f / 36.0f;   // (1/9) * (1/4)

    #pragma unroll 1
    for (int g = 0; g < Gn; g++) {
        u64 P1[CPG], Sv[CPG], Dd[CPG];
        float Fv[CPG];
        float sF2 = 0.0f;

        #pragma unroll
        for (int ci = 0; ci < CPG; ci++) {
            const int rb = rowbase0 + (g * CPG + ci) * HW;
            const float* pl = fls + rb;
            const float* pr = frs + rb;

            const float L0 = vL0 ? __ldg(pl + n_l)     : 0.0f;
            const float L1 = vL1 ? __ldg(pl + n_l + 1) : 0.0f;
            const float L2 = vL2 ? __ldg(pl + n_l + 2) : 0.0f;
            const float R0 = vR0 ? __ldg(pr + n_r)     : 0.0f;
            const float R1 = vR1 ? __ldg(pr + n_r + 1) : 0.0f;
            const float R2 = vR2 ? __ldg(pr + n_r + 2) : 0.0f;
            const float F  = __ldg(fref + rb + w);

            P1[ci] = pk(L1, R1);
            Sv[ci] = pk(0.5f * (L2 - L0),        0.5f * (R2 - R0));
            Dd[ci] = pk(0.5f * (L2 + L0) - L1,   0.5f * (R2 + R0) - R1);
            Fv[ci] = F;
            sF2 = fmaf(F, F, sF2);
        }

        const float bq = k2 * sF2;
        u64 t2 = t02;

        #pragma unroll
        for (int d = 0; d < 9; d++) {
            const u64 at2 = t2 & amask;            // (|t_l|, |t_r|)

            float acc1 = 0.0f;
            u64   acc2 = 0ull;
            #pragma unroll
            for (int ci = 0; ci < CPG; ci++) {
                const u64 lw = ffma2(t2, Sv[ci],
                               ffma2(at2, Dd[ci], P1[ci]));
                acc2 = ffma2(lw, lw, acc2);
                float wl, wr; upk(wl, wr, lw);
                const float s1 = (wl + wr) + Fv[ci];
                acc1 = fmaf(s1, s1, acc1);
            }
            t2 = add2(t2, step2);

            float a2l, a2r; upk(a2l, a2r, acc2);
            const float cost = fmaf(-k1, acc1, fmaf(k2, a2l + a2r, bq));
            __stcg(outp + (g * Dn + d) * HW, cost);
        }
    }
}

extern "C" void kernel_launch(void* const* d_in, const int* in_sizes, int n_in,
                              void* d_out, int out_size)
{
    const float* fref  = (const float*)d_in[0];
    const float* fls   = (const float*)d_in[1];
    const float* frs   = (const float*)d_in[2];
    const float* dinit = (const float*)d_in[3];
    float* out = (float*)d_out;

    cost_volume_kernel<<<(Bn * HW) / 256, 256>>>(fref, fls, frs, dinit, out);
}

// round 5
// speedup vs baseline: 1.0052x; 1.0052x over previous
#include <cuda_runtime.h>

// Cost volume s2: B=4, C=32, H=W=256, D=9, 8 groups of 4 channels.
// y-offset 0 -> 1D lerp in x; res span 0.8 < 1 px -> 3 taps/side cover all d.
// Abs-form hat lerp: w = P1 + t*S + |t|*Dd  (S=(P2-P0)/2, Dd=(P2+P0)/2-P1).
// Cross-term variance: k2=1/12, k1=1/36 => cost = (1/18) *
//   ( Sum(wl^2+wr^2) + Sum F^2 - Sum wl*wr - Sum F*(wl+wr) )
// F*(wl,wr) accumulated packed -> 5 issue slots per (d,channel), 4 packed.
// Group loop software-pipelined: next group's 28 taps prefetched into regs.

typedef unsigned long long u64;

constexpr int Wd = 256, Cn = 32, Bn = 4, Dn = 9, Gn = 8, CPG = 4;
constexpr int HW = 256 * 256;

__device__ __forceinline__ u64 pk(float a, float b) {
    u64 r; asm("mov.b64 %0, {%1, %2};" : "=l"(r) : "f"(a), "f"(b)); return r;
}
__device__ __forceinline__ void upk(float& a, float& b, u64 v) {
    asm("mov.b64 {%0, %1}, %2;" : "=f"(a), "=f"(b) : "l"(v));
}
__device__ __forceinline__ u64 ffma2(u64 a, u64 b, u64 c) {
    u64 d; asm("fma.rn.f32x2 %0, %1, %2, %3;" : "=l"(d) : "l"(a), "l"(b), "l"(c));
    return d;
}
__device__ __forceinline__ u64 add2(u64 a, u64 b) {
    u64 d; asm("add.rn.f32x2 %0, %1, %2;" : "=l"(d) : "l"(a), "l"(b));
    return d;
}

__global__ __launch_bounds__(256, 3) void cost_volume_kernel(
    const float* __restrict__ fref,
    const float* __restrict__ fls,
    const float* __restrict__ frs,
    const float* __restrict__ dinit,
    float* __restrict__ out)
{
    const int idx = blockIdx.x * 256 + threadIdx.x;   // B*H*W = 262144
    const int b  = idx >> 16;
    const int hw = idx & (HW - 1);
    const int w  = idx & (Wd - 1);

    const float disp = __ldg(dinit + idx);
    const float wf = (float)w;

    // Left taps at n_l..n_l+2, n_l = floor(x_l at d=0); x_l increases with d.
    const float xl0 = wf + disp - 0.4f;
    const float fll = floorf(xl0);
    const int   n_l = (int)fll;
    const float tl0 = xl0 - fll - 1.0f;            // t_l at d=0, in [-1, 0)

    // Right taps at n_r..n_r+2, n_r = floor(x_r at d=8); x_r decreases with d.
    const float xr0 = wf - disp + 0.4f;            // x_r at d=0 (max over d)
    const float flr = floorf(xr0 - 0.8f);          // floor of min x_r (d=8)
    const int   n_r = (int)flr;
    const float tr0 = xr0 - flr - 1.0f;            // t_r at d=0

    const u64 t02   = pk(tl0, tr0);
    const u64 step2 = pk(0.1f, -0.1f);
    const u64 amask = 0x7FFFFFFF7FFFFFFFull;

    const bool vL0 = (unsigned)(n_l)     < (unsigned)Wd;
    const bool vL1 = (unsigned)(n_l + 1) < (unsigned)Wd;
    const bool vL2 = (unsigned)(n_l + 2) < (unsigned)Wd;
    const bool vR0 = (unsigned)(n_r)     < (unsigned)Wd;
    const bool vR1 = (unsigned)(n_r + 1) < (unsigned)Wd;
    const bool vR2 = (unsigned)(n_r + 2) < (unsigned)Wd;

    const int rowbase0 = b * Cn * HW + (hw - w);   // channel-0 row start
    float* outp = out + b * (Gn * Dn * HW) + hw;

    const float c18 = 1.0f / 18.0f;

    // Raw tap registers (double-buffer role: consumed at group head, refilled
    // with next group's taps before the compute loop).
    float rL0[CPG], rL1[CPG], rL2[CPG], rR0[CPG], rR1[CPG], rR2[CPG], rF[CPG];

    auto LOADG = [&](int gg) {
        #pragma unroll
        for (int ci = 0; ci < CPG; ci++) {
            const int rb = rowbase0 + (gg * CPG + ci) * HW;
            const float* pl = fls + rb;
            const float* pr = frs + rb;
            rL0[ci] = vL0 ? __ldg(pl + n_l)     : 0.0f;
            rL1[ci] = vL1 ? __ldg(pl + n_l + 1) : 0.0f;
            rL2[ci] = vL2 ? __ldg(pl + n_l + 2) : 0.0f;
            rR0[ci] = vR0 ? __ldg(pr + n_r)     : 0.0f;
            rR1[ci] = vR1 ? __ldg(pr + n_r + 1) : 0.0f;
            rR2[ci] = vR2 ? __ldg(pr + n_r + 2) : 0.0f;
            rF[ci]  = __ldg(fref + rb + w);
        }
    };

    LOADG(0);

    #pragma unroll 1
    for (int g = 0; g < Gn; g++) {
        u64 P1[CPG], Sv[CPG], Dd[CPG], Fb[CPG];
        float sFg = 0.0f;

        #pragma unroll
        for (int ci = 0; ci < CPG; ci++) {
            const float L0 = rL0[ci], L1 = rL1[ci], L2 = rL2[ci];
            const float R0 = rR0[ci], R1 = rR1[ci], R2 = rR2[ci];
            const float F  = rF[ci];
            P1[ci] = pk(L1, R1);
            Sv[ci] = pk(0.5f * (L2 - L0), 0.5f * (R2 - R0));
            Dd[ci] = pk(fmaf(0.5f, L2 + L0, -L1), fmaf(0.5f, R2 + R0, -R1));
            Fb[ci] = pk(F, F);
            sFg = fmaf(F, F, sFg);
        }

        if (g + 1 < Gn) LOADG(g + 1);   // prefetch next group's taps (covered
                                        // by this group's 9*4 compute body)

        u64 t2 = t02;
        #pragma unroll
        for (int d = 0; d < 9; d++) {
            const u64 at2 = t2 & amask;            // (|t_l|, |t_r|)

            u64 acc2 = 0ull, accF = 0ull;
            float ax = 0.0f;
            #pragma unroll
            for (int ci = 0; ci < CPG; ci++) {
                const u64 lw = ffma2(t2, Sv[ci],
                               ffma2(at2, Dd[ci], P1[ci]));
                acc2 = ffma2(lw, lw, acc2);        // (Swl^2, Swr^2)
                accF = ffma2(Fb[ci], lw, accF);    // (SFwl, SFwr)
                float wl, wr; upk(wl, wr, lw);
                ax = fmaf(wl, wr, ax);             // Swl*wr
            }
            t2 = add2(t2, step2);

            float a2l, a2r; upk(a2l, a2r, acc2);
            float aFl, aFr; upk(aFl, aFr, accF);
            const float hq = (a2l + a2r) + (sFg - ax);
            const float hf = aFl + aFr;
            const float cost = (hq - hf) * c18;
            __stcg(outp + (g * Dn + d) * HW, cost);
        }
    }
}

extern "C" void kernel_launch(void* const* d_in, const int* in_sizes, int n_in,
                              void* d_out, int out_size)
{
    const float* fref  = (const float*)d_in[0];
    const float* fls   = (const float*)d_in[1];
    const float* frs   = (const float*)d_in[2];
    const float* dinit = (const float*)d_in[3];
    float* out = (float*)d_out;

    cost_volume_kernel<<<(Bn * HW) / 256, 256>>>(fref, fls, frs, dinit, out);
}